// round 1
// baseline (speedup 1.0000x reference)
#include <cuda_runtime.h>

#define B_  4
#define C_  512
#define CI_ 256
#define N_  4096
#define EPS_ 1e-5f

// ---------------- scratch (device globals: allowed; no allocs) ----------------
__device__ float g_buf [B_ * CI_ * N_];          // 16 MB
__device__ float th_buf[B_ * CI_ * N_];          // 16 MB
__device__ float ph_buf[B_ * CI_ * N_];          // 16 MB
__device__ float y_buf [B_ * CI_ * N_];          // 16 MB
__device__ float Wy_buf[B_ * C_  * N_];          // 32 MB
__device__ float R_buf [67108864];               // B*N*N = 4*4096*4096 floats = 256 MB
__device__ float bn_mean[C_];
__device__ float bn_rstd[C_];

// ---------------------------------------------------------------------------
// Generic 128x128x8 SGEMM, 256 threads, 8x8 per-thread register tile.
//   C[i][j] = alpha * sum_k A(i,k) * B(k,j) + bias[i]
// A_KM = true  : A stored [K, M] row-major (ld = M)   -> direct smem load
// A_KM = false : A stored [M, K] row-major (ld = K)   -> transpose on load
// B_NK = false : B stored [K, N] row-major (ld = N)   -> direct smem load
// B_NK = true  : B stored [N, K] row-major (ld = K)   -> transpose on load
// Batched via blockIdx.z with element strides sA/sB/sC.
// All dims assumed multiples of tile sizes (true for this problem).
// ---------------------------------------------------------------------------
template <bool A_KM, bool B_NK>
__global__ __launch_bounds__(256)
void sgemm_kernel(const float* __restrict__ A,
                  const float* __restrict__ B,
                  float* __restrict__ C,
                  const float* __restrict__ bias,
                  int M, int N, int K, float alpha,
                  long sA, long sB, long sC)
{
    const int bx = blockIdx.x;   // N tile
    const int by = blockIdx.y;   // M tile
    const int bz = blockIdx.z;   // batch
    A += (long)bz * sA;
    B += (long)bz * sB;
    C += (long)bz * sC;

    __shared__ float As[8][128];
    __shared__ float Bs[8][128];

    const int tid = threadIdx.x;
    const int tx = tid & 15;     // 0..15 -> output col group
    const int ty = tid >> 4;     // 0..15 -> output row group

    // loader indices
    const int rT  = tid >> 1;           // 0..127 (for [X, K] transposed loads)
    const int cT  = (tid & 1) * 4;      // 0 or 4
    const int rK  = tid >> 5;           // 0..7   (for [K, X] direct loads)
    const int cM  = (tid & 31) * 4;     // 0..124

    float acc[8][8];
#pragma unroll
    for (int i = 0; i < 8; i++)
#pragma unroll
        for (int j = 0; j < 8; j++) acc[i][j] = 0.f;

    for (int k0 = 0; k0 < K; k0 += 8) {
        if (A_KM) {
            const float4 a4 = *(const float4*)&A[(long)(k0 + rK) * M + by * 128 + cM];
            *(float4*)&As[rK][cM] = a4;
        } else {
            const float4 a4 = *(const float4*)&A[(long)(by * 128 + rT) * K + k0 + cT];
            As[cT + 0][rT] = a4.x;
            As[cT + 1][rT] = a4.y;
            As[cT + 2][rT] = a4.z;
            As[cT + 3][rT] = a4.w;
        }
        if (B_NK) {
            const float4 b4 = *(const float4*)&B[(long)(bx * 128 + rT) * K + k0 + cT];
            Bs[cT + 0][rT] = b4.x;
            Bs[cT + 1][rT] = b4.y;
            Bs[cT + 2][rT] = b4.z;
            Bs[cT + 3][rT] = b4.w;
        } else {
            const float4 b4 = *(const float4*)&B[(long)(k0 + rK) * N + bx * 128 + cM];
            *(float4*)&Bs[rK][cM] = b4;
        }
        __syncthreads();

#pragma unroll
        for (int k = 0; k < 8; k++) {
            float ar[8], br[8];
            *(float4*)&ar[0] = *(const float4*)&As[k][ty * 8];
            *(float4*)&ar[4] = *(const float4*)&As[k][ty * 8 + 4];
            *(float4*)&br[0] = *(const float4*)&Bs[k][tx * 8];
            *(float4*)&br[4] = *(const float4*)&Bs[k][tx * 8 + 4];
#pragma unroll
            for (int i = 0; i < 8; i++)
#pragma unroll
                for (int j = 0; j < 8; j++)
                    acc[i][j] += ar[i] * br[j];
        }
        __syncthreads();
    }

#pragma unroll
    for (int i = 0; i < 8; i++) {
        const int row = by * 128 + ty * 8 + i;
        const float bv = bias ? bias[row] : 0.f;
#pragma unroll
        for (int j = 0; j < 8; j += 4) {
            float4 o;
            o.x = alpha * acc[i][j + 0] + bv;
            o.y = alpha * acc[i][j + 1] + bv;
            o.z = alpha * acc[i][j + 2] + bv;
            o.w = alpha * acc[i][j + 3] + bv;
            *(float4*)&C[(long)row * N + bx * 128 + tx * 8 + j] = o;
        }
    }
}

// ---------------------------------------------------------------------------
// BatchNorm stats: per channel c over (B, N). Biased variance (torch BN).
// ---------------------------------------------------------------------------
__global__ __launch_bounds__(256)
void bn_stats_kernel(const float* __restrict__ Wy)
{
    const int c = blockIdx.x;
    float s = 0.f, ss = 0.f;
    for (int i = threadIdx.x; i < B_ * N_; i += 256) {
        const int b = i >> 12;          // / 4096
        const int n = i & (N_ - 1);
        const float x = Wy[((long)b * C_ + c) * N_ + n];
        s += x;
        ss += x * x;
    }
    __shared__ float sh_s[256], sh_q[256];
    sh_s[threadIdx.x] = s;
    sh_q[threadIdx.x] = ss;
    __syncthreads();
    for (int o = 128; o > 0; o >>= 1) {
        if (threadIdx.x < o) {
            sh_s[threadIdx.x] += sh_s[threadIdx.x + o];
            sh_q[threadIdx.x] += sh_q[threadIdx.x + o];
        }
        __syncthreads();
    }
    if (threadIdx.x == 0) {
        const float inv = 1.f / (float)(B_ * N_);
        const float m   = sh_s[0] * inv;
        const float var = fmaxf(sh_q[0] * inv - m * m, 0.f);
        bn_mean[c] = m;
        bn_rstd[c] = rsqrtf(var + EPS_);
    }
}

// ---------------------------------------------------------------------------
// Fused BN apply + affine + residual. float4 vectorized.
// out = (Wy - mean) * rstd * gamma + beta + v
// ---------------------------------------------------------------------------
__global__ __launch_bounds__(256)
void bn_apply_kernel(const float* __restrict__ Wy,
                     const float* __restrict__ v,
                     const float* __restrict__ gamma,
                     const float* __restrict__ beta,
                     float* __restrict__ out)
{
    const long idx = (long)blockIdx.x * 256 + threadIdx.x;   // float4 index
    const long total4 = (long)B_ * C_ * N_ / 4;
    if (idx >= total4) return;
    const int c = (int)((idx * 4 / N_) % C_);
    const float sc = bn_rstd[c] * gamma[c];
    const float sh = beta[c] - bn_mean[c] * sc;
    const float4 w  = ((const float4*)Wy)[idx];
    const float4 vv = ((const float4*)v)[idx];
    float4 o;
    o.x = w.x * sc + sh + vv.x;
    o.y = w.y * sc + sh + vv.y;
    o.z = w.z * sc + sh + vv.z;
    o.w = w.w * sc + sh + vv.w;
    ((float4*)out)[idx] = o;
}

// ---------------------------------------------------------------------------
extern "C" void kernel_launch(void* const* d_in, const int* in_sizes, int n_in,
                              void* d_out, int out_size)
{
    const float* v     = (const float*)d_in[0];
    const float* Wg    = (const float*)d_in[1];
    const float* bg    = (const float*)d_in[2];
    const float* Wth   = (const float*)d_in[3];
    const float* bth   = (const float*)d_in[4];
    const float* Wph   = (const float*)d_in[5];
    const float* bph   = (const float*)d_in[6];
    const float* Ww    = (const float*)d_in[7];
    const float* bw    = (const float*)d_in[8];
    const float* gamma = (const float*)d_in[9];
    const float* beta  = (const float*)d_in[10];
    float* out = (float*)d_out;

    float *g, *th, *ph, *y, *Wy, *R;
    cudaGetSymbolAddress((void**)&g,  g_buf);
    cudaGetSymbolAddress((void**)&th, th_buf);
    cudaGetSymbolAddress((void**)&ph, ph_buf);
    cudaGetSymbolAddress((void**)&y,  y_buf);
    cudaGetSymbolAddress((void**)&Wy, Wy_buf);
    cudaGetSymbolAddress((void**)&R,  R_buf);

    const dim3 tpb(256);
    const long sV  = (long)C_  * N_;   // v per-batch stride
    const long sCi = (long)CI_ * N_;   // [Ci,N] per-batch stride
    const long sR  = (long)N_  * N_;   // R per-batch stride
    const long sC  = (long)C_  * N_;   // [C,N] per-batch stride

    // 1) projections: out[ci][n] = sum_c W[ci][c] * v[c][n] + b[ci]
    {
        dim3 grid(N_ / 128, CI_ / 128, B_);
        sgemm_kernel<false, false><<<grid, tpb>>>(Wg,  v, g,  bg,  CI_, N_, C_, 1.f, 0, sV, sCi);
        sgemm_kernel<false, false><<<grid, tpb>>>(Wth, v, th, bth, CI_, N_, C_, 1.f, 0, sV, sCi);
        sgemm_kernel<false, false><<<grid, tpb>>>(Wph, v, ph, bph, CI_, N_, C_, 1.f, 0, sV, sCi);
    }

    // 2) R[n][m] = (1/N) * sum_c th[c][n] * ph[c][m]   (TN: A=[K,M], B=[K,N])
    {
        dim3 grid(N_ / 128, N_ / 128, B_);
        sgemm_kernel<true, false><<<grid, tpb>>>(th, ph, R, nullptr, N_, N_, CI_, 1.f / (float)N_, sCi, sCi, sR);
    }

    // 3) y[ci][n] = sum_m g[ci][m] * R[n][m]   (NT: A=[M,K], B=[N,K])
    {
        dim3 grid(N_ / 128, CI_ / 128, B_);
        sgemm_kernel<false, true><<<grid, tpb>>>(g, R, y, nullptr, CI_, N_, N_, 1.f, sCi, sR, sCi);
    }

    // 4) Wy[c][n] = sum_ci Ww[c][ci] * y[ci][n] + bw[c]
    {
        dim3 grid(N_ / 128, C_ / 128, B_);
        sgemm_kernel<false, false><<<grid, tpb>>>(Ww, y, Wy, bw, C_, N_, CI_, 1.f, 0, sCi, sC);
    }

    // 5) BN stats per channel
    bn_stats_kernel<<<C_, 256>>>(Wy);

    // 6) BN apply + affine + residual
    {
        const long total4 = (long)B_ * C_ * N_ / 4;
        const int blocks = (int)((total4 + 255) / 256);
        bn_apply_kernel<<<blocks, 256>>>(Wy, v, gamma, beta, out);
    }
}

// round 3
// speedup vs baseline: 2.5719x; 2.5719x over previous
#include <cuda_runtime.h>
#include <cuda_fp16.h>
#include <cstdint>

#define B_  4
#define C_  512
#define CI_ 256
#define N_  4096
#define EPS_ 1e-5f
#define RSCALE 64.0f

// ------------------------- device scratch (no allocs) -------------------------
__device__ float vT_buf[B_ * N_ * C_];            // 32 MB  [B,N,C]
__device__ float g_buf [B_ * CI_ * N_];           // 16 MB  [B,Ci,N]
__device__ float th_buf[B_ * N_ * CI_];           // 16 MB  [B,N,Ci]
__device__ float ph_buf[B_ * N_ * CI_];           // 16 MB  [B,N,Ci]
__device__ float y_buf [B_ * N_ * CI_];           // 16 MB  [B,N,Ci]
__device__ float Wy_buf[B_ * C_ * N_];            // 32 MB  [B,C,N]
__device__ float R_buf [(long)B_ * N_ * N_];      // 256 MB [B,N,N]  (stores R*RSCALE)
__device__ float bn_mean[C_];
__device__ float bn_rstd[C_];

// ------------------------------- GEMM config ----------------------------------
#define BM 128
#define BN 128
#define BK 32
#define PITCH 40                        // halves per smem row (80B) -> conflict-free
#define TILE_HALVES (128 * PITCH)       // 5120
#define BUF_HALVES  (4 * TILE_HALVES)   // Ah, Al, Bh, Bl
#define SMEM_GEMM_BYTES (2 * BUF_HALVES * 2 + 1024)

__device__ __forceinline__ void mma16816(float* c, const uint32_t* a, const uint32_t* b) {
    asm volatile(
        "mma.sync.aligned.m16n8k16.row.col.f32.f16.f16.f32 "
        "{%0,%1,%2,%3}, {%4,%5,%6,%7}, {%8,%9}, {%0,%1,%2,%3};"
        : "+f"(c[0]), "+f"(c[1]), "+f"(c[2]), "+f"(c[3])
        : "r"(a[0]), "r"(a[1]), "r"(a[2]), "r"(a[3]), "r"(b[0]), "r"(b[1]));
}

__device__ __forceinline__ uint32_t lds_u32(const half* p, int r, int c) {
    return *(const uint32_t*)&p[r * PITCH + c];
}

// split fp32x4 -> hi/lo fp16 pairs, store to smem (lo at +TILE_HALVES)
__device__ __forceinline__ void split_store(half* base, int idx, float4 x) {
    half2 h01 = __floats2half2_rn(x.x, x.y);
    half2 h23 = __floats2half2_rn(x.z, x.w);
    float2 f01 = __half22float2(h01);
    float2 f23 = __half22float2(h23);
    half2 l01 = __floats2half2_rn(x.x - f01.x, x.y - f01.y);
    half2 l23 = __floats2half2_rn(x.z - f23.x, x.w - f23.y);
    *(half2*)&base[idx]     = h01;
    *(half2*)&base[idx + 2] = h23;
    *(half2*)&base[TILE_HALVES + idx]     = l01;
    *(half2*)&base[TILE_HALVES + idx + 2] = l23;
}

// ------------------------------------------------------------------------------
// D[M,Nt] = alpha * A[M,K] @ B[Nt,K]^T + biasM[row] + biasN[col]
// A, B row-major, K contiguous. grid = (Nt/128, M/128, batch). 256 threads.
// fp16x3: hi*hi + lo*hi + hi*lo, fp32 accumulate -> ~1e-7 relative error.
// ------------------------------------------------------------------------------
__global__ __launch_bounds__(256, 1)
void gemm_fp16x3(const float* __restrict__ A, const float* __restrict__ Bm,
                 float* __restrict__ D,
                 const float* __restrict__ biasM, const float* __restrict__ biasN,
                 int M, int Nt, int K, float alpha,
                 long sA, long sB, long sD)
{
    extern __shared__ char smem[];
    half*  sh  = (half*)smem;
    float* sBM = (float*)(smem + 2 * BUF_HALVES * 2);
    float* sBN = sBM + 128;

    const int tid = threadIdx.x;
    const int bx = blockIdx.x, by = blockIdx.y, bz = blockIdx.z;
    A  += (long)bz * sA + (long)(by * BM) * K;
    Bm += (long)bz * sB + (long)(bx * BN) * K;
    D  += (long)bz * sD;

    if (tid < 128) {
        sBM[tid] = biasM ? biasM[by * BM + tid] : 0.f;
        sBN[tid] = biasN ? biasN[bx * BN + tid] : 0.f;
    }

    const int sf = tid & 7;       // k-chunk (4 floats)
    const int sr = tid >> 3;      // 0..31 (row base)
    const int nIter = K / BK;

    float4 ra[4], rb[4];
#pragma unroll
    for (int i = 0; i < 4; ++i) {
        ra[i] = *(const float4*)&A[(long)(sr + 32 * i) * K + sf * 4];
        rb[i] = *(const float4*)&Bm[(long)(sr + 32 * i) * K + sf * 4];
    }
    {
        half* Ab = sh;                       // buf 0
        half* Bb = sh + 2 * TILE_HALVES;
#pragma unroll
        for (int i = 0; i < 4; ++i) {
            const int idx = (sr + 32 * i) * PITCH + sf * 4;
            split_store(Ab, idx, ra[i]);
            split_store(Bb, idx, rb[i]);
        }
    }
    __syncthreads();

    float acc[4][4][4];
#pragma unroll
    for (int mi = 0; mi < 4; ++mi)
#pragma unroll
        for (int ni = 0; ni < 4; ++ni)
#pragma unroll
            for (int q = 0; q < 4; ++q) acc[mi][ni][q] = 0.f;

    const int wid = tid >> 5, lid = tid & 31;
    const int wm = (wid >> 2) * 64;   // warp m offset (0/64)
    const int wn = (wid & 3) * 32;    // warp n offset
    const int g = lid >> 2;           // group id 0..7
    const int t = lid & 3;            // thread in group

    for (int it = 0; it < nIter; ++it) {
        const int buf = it & 1;
        const bool hasNext = (it + 1 < nIter);
        if (hasNext) {
            const int k0 = (it + 1) * BK;
#pragma unroll
            for (int i = 0; i < 4; ++i) {
                ra[i] = *(const float4*)&A[(long)(sr + 32 * i) * K + k0 + sf * 4];
                rb[i] = *(const float4*)&Bm[(long)(sr + 32 * i) * K + k0 + sf * 4];
            }
        }

        const half* Ah = sh + buf * BUF_HALVES;
        const half* Al = Ah + TILE_HALVES;
        const half* Bh = Ah + 2 * TILE_HALVES;
        const half* Bl = Ah + 3 * TILE_HALVES;

#pragma unroll
        for (int kk = 0; kk < 2; ++kk) {
            const int kc = kk * 16 + t * 2;
            uint32_t ah[4][4], al[4][4];
#pragma unroll
            for (int mi = 0; mi < 4; ++mi) {
                const int r = wm + mi * 16 + g;
                ah[mi][0] = lds_u32(Ah, r,     kc);
                ah[mi][1] = lds_u32(Ah, r + 8, kc);
                ah[mi][2] = lds_u32(Ah, r,     kc + 8);
                ah[mi][3] = lds_u32(Ah, r + 8, kc + 8);
                al[mi][0] = lds_u32(Al, r,     kc);
                al[mi][1] = lds_u32(Al, r + 8, kc);
                al[mi][2] = lds_u32(Al, r,     kc + 8);
                al[mi][3] = lds_u32(Al, r + 8, kc + 8);
            }
            uint32_t bh[4][2], bl[4][2];
#pragma unroll
            for (int ni = 0; ni < 4; ++ni) {
                const int r = wn + ni * 8 + g;
                bh[ni][0] = lds_u32(Bh, r, kc);
                bh[ni][1] = lds_u32(Bh, r, kc + 8);
                bl[ni][0] = lds_u32(Bl, r, kc);
                bl[ni][1] = lds_u32(Bl, r, kc + 8);
            }
#pragma unroll
            for (int mi = 0; mi < 4; ++mi)
#pragma unroll
                for (int ni = 0; ni < 4; ++ni) {
                    mma16816(acc[mi][ni], ah[mi], bh[ni]);
                    mma16816(acc[mi][ni], al[mi], bh[ni]);
                    mma16816(acc[mi][ni], ah[mi], bl[ni]);
                }
        }

        if (hasNext) {
            half* Ab = sh + (buf ^ 1) * BUF_HALVES;
            half* Bb = Ab + 2 * TILE_HALVES;
#pragma unroll
            for (int i = 0; i < 4; ++i) {
                const int idx = (sr + 32 * i) * PITCH + sf * 4;
                split_store(Ab, idx, ra[i]);
                split_store(Bb, idx, rb[i]);
            }
        }
        __syncthreads();
    }

    // epilogue
#pragma unroll
    for (int mi = 0; mi < 4; ++mi) {
        const int row0 = wm + mi * 16 + g;
        const float bm0 = sBM[row0], bm1 = sBM[row0 + 8];
        const long gr0 = (long)(by * BM + row0) * Nt + bx * BN;
        const long gr1 = gr0 + 8L * Nt;
#pragma unroll
        for (int ni = 0; ni < 4; ++ni) {
            const int col = wn + ni * 8 + t * 2;
            const float bn0 = sBN[col], bn1 = sBN[col + 1];
            float2 o0, o1;
            o0.x = alpha * acc[mi][ni][0] + bm0 + bn0;
            o0.y = alpha * acc[mi][ni][1] + bm0 + bn1;
            o1.x = alpha * acc[mi][ni][2] + bm1 + bn0;
            o1.y = alpha * acc[mi][ni][3] + bm1 + bn1;
            *(float2*)&D[gr0 + col] = o0;
            *(float2*)&D[gr1 + col] = o1;
        }
    }
}

// ------------------------------------------------------------------------------
// v [B,C,N] -> vT [B,N,C]
__global__ __launch_bounds__(256)
void transpose_kernel(const float* __restrict__ v, float* __restrict__ o)
{
    __shared__ float t[32][33];
    const int b = blockIdx.z;
    const int n0 = blockIdx.x * 32, c0 = blockIdx.y * 32;
    const int tx = threadIdx.x, ty = threadIdx.y;   // 32 x 8
#pragma unroll
    for (int i = 0; i < 4; ++i)
        t[ty + 8 * i][tx] = v[((long)b * C_ + c0 + ty + 8 * i) * N_ + n0 + tx];
    __syncthreads();
#pragma unroll
    for (int i = 0; i < 4; ++i)
        o[((long)b * N_ + n0 + ty + 8 * i) * C_ + c0 + tx] = t[tx][ty + 8 * i];
}

// ------------------------------------------------------------------------------
__global__ __launch_bounds__(256)
void bn_stats_kernel(const float* __restrict__ Wy)
{
    const int c = blockIdx.x;
    float s = 0.f, ss = 0.f;
    for (int i = threadIdx.x; i < B_ * N_; i += 256) {
        const int b = i >> 12;
        const int n = i & (N_ - 1);
        const float x = Wy[((long)b * C_ + c) * N_ + n];
        s += x;
        ss += x * x;
    }
    __shared__ float sh_s[256], sh_q[256];
    sh_s[threadIdx.x] = s;
    sh_q[threadIdx.x] = ss;
    __syncthreads();
    for (int o = 128; o > 0; o >>= 1) {
        if (threadIdx.x < o) {
            sh_s[threadIdx.x] += sh_s[threadIdx.x + o];
            sh_q[threadIdx.x] += sh_q[threadIdx.x + o];
        }
        __syncthreads();
    }
    if (threadIdx.x == 0) {
        const float inv = 1.f / (float)(B_ * N_);
        const float m   = sh_s[0] * inv;
        const float var = fmaxf(sh_q[0] * inv - m * m, 0.f);
        bn_mean[c] = m;
        bn_rstd[c] = rsqrtf(var + EPS_);
    }
}

__global__ __launch_bounds__(256)
void bn_apply_kernel(const float* __restrict__ Wy,
                     const float* __restrict__ v,
                     const float* __restrict__ gamma,
                     const float* __restrict__ beta,
                     float* __restrict__ out)
{
    const long idx = (long)blockIdx.x * 256 + threadIdx.x;   // float4 index
    const long total4 = (long)B_ * C_ * N_ / 4;
    if (idx >= total4) return;
    const int c = (int)((idx * 4 / N_) % C_);
    const float sc = bn_rstd[c] * gamma[c];
    const float sh = beta[c] - bn_mean[c] * sc;
    const float4 w  = ((const float4*)Wy)[idx];
    const float4 vv = ((const float4*)v)[idx];
    float4 o;
    o.x = w.x * sc + sh + vv.x;
    o.y = w.y * sc + sh + vv.y;
    o.z = w.z * sc + sh + vv.z;
    o.w = w.w * sc + sh + vv.w;
    ((float4*)out)[idx] = o;
}

// ------------------------------------------------------------------------------
extern "C" void kernel_launch(void* const* d_in, const int* in_sizes, int n_in,
                              void* d_out, int out_size)
{
    const float* v     = (const float*)d_in[0];
    const float* Wg    = (const float*)d_in[1];
    const float* bg    = (const float*)d_in[2];
    const float* Wth   = (const float*)d_in[3];
    const float* bth   = (const float*)d_in[4];
    const float* Wph   = (const float*)d_in[5];
    const float* bph   = (const float*)d_in[6];
    const float* Ww    = (const float*)d_in[7];
    const float* bw    = (const float*)d_in[8];
    const float* gamma = (const float*)d_in[9];
    const float* beta  = (const float*)d_in[10];
    float* out = (float*)d_out;

    float *vT, *g, *th, *ph, *y, *Wy, *R;
    cudaGetSymbolAddress((void**)&vT, vT_buf);
    cudaGetSymbolAddress((void**)&g,  g_buf);
    cudaGetSymbolAddress((void**)&th, th_buf);
    cudaGetSymbolAddress((void**)&ph, ph_buf);
    cudaGetSymbolAddress((void**)&y,  y_buf);
    cudaGetSymbolAddress((void**)&Wy, Wy_buf);
    cudaGetSymbolAddress((void**)&R,  R_buf);

    cudaFuncSetAttribute(gemm_fp16x3, cudaFuncAttributeMaxDynamicSharedMemorySize, SMEM_GEMM_BYTES);

    const long sVT = (long)N_ * C_;
    const long sNC = (long)N_ * CI_;   // [N,Ci]
    const long sCN = (long)CI_ * N_;   // [Ci,N]
    const long sR  = (long)N_ * N_;
    const long sC  = (long)C_ * N_;

    // 0) v -> vT [B,N,C]
    transpose_kernel<<<dim3(N_ / 32, C_ / 32, B_), dim3(32, 8)>>>(v, vT);

    // 1) th[n,ci] = vT[n,:] . Wth[ci,:] + bth[ci]
    gemm_fp16x3<<<dim3(CI_ / 128, N_ / 128, B_), 256, SMEM_GEMM_BYTES>>>(
        vT, Wth, th, nullptr, bth, N_, CI_, C_, 1.f, sVT, 0, sNC);
    // 2) ph[n,ci]
    gemm_fp16x3<<<dim3(CI_ / 128, N_ / 128, B_), 256, SMEM_GEMM_BYTES>>>(
        vT, Wph, ph, nullptr, bph, N_, CI_, C_, 1.f, sVT, 0, sNC);
    // 3) g[ci,n] = Wg[ci,:] . vT[n,:] + bg[ci]
    gemm_fp16x3<<<dim3(N_ / 128, CI_ / 128, B_), 256, SMEM_GEMM_BYTES>>>(
        Wg, vT, g, bg, nullptr, CI_, N_, C_, 1.f, 0, sVT, sCN);
    // 4) R[n,m] = (RSCALE/N) th[n,:] . ph[m,:]   (scaled to keep lo-split in fp16-normal range)
    gemm_fp16x3<<<dim3(N_ / 128, N_ / 128, B_), 256, SMEM_GEMM_BYTES>>>(
        th, ph, R, nullptr, nullptr, N_, N_, CI_, RSCALE / (float)N_, sNC, sNC, sR);
    // 5) y[n,ci] = (1/RSCALE) R[n,:] . g[ci,:]
    gemm_fp16x3<<<dim3(CI_ / 128, N_ / 128, B_), 256, SMEM_GEMM_BYTES>>>(
        R, g, y, nullptr, nullptr, N_, CI_, N_, 1.f / RSCALE, sR, sCN, sNC);
    // 6) Wy[c,n] = Ww[c,:] . y[n,:] + bw[c]
    gemm_fp16x3<<<dim3(N_ / 128, C_ / 128, B_), 256, SMEM_GEMM_BYTES>>>(
        Ww, y, Wy, bw, nullptr, C_, N_, CI_, 1.f, 0, sNC, sC);

    // 7) BN stats + apply + residual
    bn_stats_kernel<<<C_, 256>>>(Wy);
    const long total4 = (long)B_ * C_ * N_ / 4;
    bn_apply_kernel<<<(int)((total4 + 255) / 256), 256>>>(Wy, v, gamma, beta, out);
}